// round 14
// baseline (speedup 1.0000x reference)
#include <cuda_runtime.h>
#include <cuda_fp16.h>
#include <math.h>
#include <float.h>
#include <stdint.h>

#define NXY     36864      // 192*192 pixels
#define ETL     16
#define NDICT   4000
#define NSLOT   8          // SE (kept) columns; data-driven, padded with -1
#define RECB    80         // bytes per record (both fp32 and fp16 layouts)
#define NQ      8          // dictionary slices
#define NREC    250        // records per slice (500 atoms)
#define ATOMS_S (2 * NREC)
#define PX      4          // pixels per thread
#define TPB     256
#define GRPPX   (TPB * PX)      // 1024 pixels per group
#define NGRP    (NXY / GRPPX)   // 36 pixel groups

#define BAND     0.040f    // covers worst-case |fp16 score - fp32 score| (<=1.5e-2) 2x
#define CAND_MAX 40

// Per-slice partial results: key = monotone(score)<<32 | (65535 - atom).
__device__ unsigned long long g_part[NQ * NXY];
// Arrival counters; atomicInc wraps at NQ -> self-resetting across replays.
__device__ unsigned int g_cnt[NGRP];

// ---- packed f32x2 helpers (Blackwell FFMA2 path) ------------------------
#define FMA_F32X2(d, a, b, c) \
    asm("fma.rn.f32x2 %0, %1, %2, %3;" : "=l"(d) : "l"(a), "l"(b), "l"(c))
#define PACK_F32X2(out, lo, hi) \
    asm("mov.b64 %0, {%1, %2};" : "=l"(out) : "f"(lo), "f"(hi))
#define UNPACK_F32X2(lo, hi, in) \
    asm("mov.b64 {%0, %1}, %2;" : "=f"(lo), "=f"(hi) : "l"(in))

__device__ __forceinline__ void get_cols(const float* __restrict__ delta_ms,
                                         int* cols) {
    int j = 0;
    for (int k = 0; k < ETL; k++) {
        if (delta_ms[k] * 1e-3f < 1e-3f && j < NSLOT) cols[j++] = k;
    }
    for (; j < NSLOT; j++) cols[j] = -1;
}

__device__ __forceinline__ unsigned int fmono(float f) {
    unsigned int u = __float_as_uint(f);
    return (u & 0x80000000u) ? ~u : (u | 0x80000000u);
}
__device__ __forceinline__ float fmono_inv(unsigned int u) {
    return (u & 0x80000000u) ? __uint_as_float(u ^ 0x80000000u)
                             : __uint_as_float(~u);
}
__device__ __forceinline__ __half2 u2h2(unsigned int u) {
    __half2 h;
    *(unsigned int*)&h = u;
    return h;
}

// Exact fp32 atom score: 4 two-lane FFMA2 partials + cross-lane combine.
// Bit-deterministic; used ONLY in verification (internal consistency).
__device__ __forceinline__ float atom_score(
    ulonglong2 wA, ulonglong2 wB, float bias, const uint64_t* sp)
{
    uint64_t acc;
    PACK_F32X2(acc, bias, 0.0f);
    FMA_F32X2(acc, wA.x, sp[0], acc);
    FMA_F32X2(acc, wA.y, sp[1], acc);
    FMA_F32X2(acc, wB.x, sp[2], acc);
    FMA_F32X2(acc, wB.y, sp[3], acc);
    float lo, hi;
    UNPACK_F32X2(lo, hi, acc);
    return lo + hi;
}

// ---------------------------------------------------------------------------
// Single fused kernel. grid = 36 pixel-groups x 8 dict-slices = 288 CTAs,
// 2 CTAs/SM (40 KB SMEM). Pass 1: branch-free fp16 screen (HFMA2, 2x MAC
// rate) recording per-record fp16 maxes. Pass 2: per-thread candidate list,
// exact fp32 rescoring. Last CTA of each pixel group merges and writes.
// ---------------------------------------------------------------------------
__global__ void __launch_bounds__(TPB, 2) fused_kernel(
    const float* __restrict__ sig,       // [NXY, ETL]
    const float* __restrict__ db_mag,    // [NDICT, ETL]
    const float* __restrict__ t2s,       // [NDICT]
    const float* __restrict__ b1s,       // [NDICT]
    const float* __restrict__ delta_ms,  // [ETL]
    float* __restrict__ out)             // [3*NXY]: t2 | b1 | min_dist
{
    // fp32: [0..32) even w0..7, [32..64) odd w0..7, [64..72) (bias_e,bias_o)
    __shared__ __align__(16) float sdict32[NREC * (RECB / 4)];   // 20 KB
    // fp16: [0..32) even 8x half2(w,w), [32..64) odd, [64..72) bias dups
    __shared__ __align__(16) char  sdict16[NREC * RECB];         // 20 KB
    __shared__ int s_last;

    const int group = blockIdx.x >> 3;   // 0..35
    const int q     = blockIdx.x & 7;    // dict slice

    int cols[NSLOT];
    get_cols(delta_ms, cols);

    // ---- Build this slice's records (normalization == reference) ----
    for (int a = threadIdx.x; a < ATOMS_S; a += TPB) {
        int ga = q * ATOMS_S + a;        // global atom index
        float v[NSLOT];
        float n2 = 0.0f;
#pragma unroll
        for (int j = 0; j < NSLOT; j++) {
            int c = cols[j];
            float x = (c >= 0) ? db_mag[ga * ETL + c] : 0.0f;
            v[j] = x;
            n2 = fmaf(x, x, n2);
        }
        float inv = 0.0f;
        if (n2 > 0.0f) {
            float r = 1.0f / sqrtf(n2);
            if (isfinite(r)) inv = r;
        }
        int ri  = a >> 1;
        int par = a & 1;                  // 0 = even atom, 1 = odd atom
        float* rec = sdict32 + ri * (RECB / 4);
        char*  hrec = sdict16 + ri * RECB;
        float d2 = 0.0f;
#pragma unroll
        for (int j = 0; j < NSLOT; j++) {
            float s = v[j] * inv;
            float w = 2.0f * s;           // w = 2 * normalized value
            rec[par * 8 + j] = w;
            *(__half2*)(hrec + par * 32 + j * 4) =
                __half2half2(__float2half(w));
            d2 = fmaf(s, s, d2);
        }
        rec[16 + par] = -d2;              // fp32 bias
        *(__half2*)(hrec + 64 + par * 4) =
            __half2half2(__float2half(-d2));
    }

    // ---- Load + normalize this thread's 4 pixels (nan_to_num semantics) ----
    float s2px[PX];
    uint64_t sp[PX][4];                   // fp32 pairs (s0,s1)..(s6,s7)
    __half2 sh01[NSLOT], sh23[NSLOT];     // fp16 pixel pairs per dim
    {
        float sval[PX][NSLOT];
#pragma unroll
        for (int u = 0; u < PX; u++) {
            int n = group * GRPPX + u * TPB + threadIdx.x;
            float m[NSLOT];
            float nm2 = 0.0f;
#pragma unroll
            for (int j = 0; j < NSLOT; j++) {
                int c = cols[j];
                float v = (c >= 0) ? sig[n * ETL + c] : 0.0f;
                m[j] = v;
                nm2 = fmaf(v, v, nm2);
            }
            float inv = 0.0f;
            if (nm2 > 0.0f) {
                float r = 1.0f / sqrtf(nm2);
                if (isfinite(r)) inv = r;
            }
            float acc = 0.0f;
#pragma unroll
            for (int j = 0; j < NSLOT; j++) {
                float s = m[j] * inv;
                sval[u][j] = s;
                acc = fmaf(s, s, acc);
            }
            s2px[u] = acc;
#pragma unroll
            for (int j = 0; j < 4; j++)
                PACK_F32X2(sp[u][j], sval[u][2 * j], sval[u][2 * j + 1]);
        }
#pragma unroll
        for (int j = 0; j < NSLOT; j++) {
            sh01[j] = __floats2half2_rn(sval[0][j], sval[1][j]);
            sh23[j] = __floats2half2_rn(sval[2][j], sval[3][j]);
        }
    }

    __syncthreads();

    // ---- Pass 1: branch-free fp16 screen ----
    __half hmx[NREC];                     // local: per-record fp16 max (4 px)
    __half2 best01 = __half2half2(__ushort_as_half(0xFBFF));  // -65504
    __half2 best23 = best01;

    const char* hbase = (const char*)sdict16;
#pragma unroll 1
    for (int i = 0; i < NREC; i++) {
        const uint4* hp = (const uint4*)(hbase + i * RECB);
        uint4 e0 = hp[0], e1 = hp[1];     // even atom w-dups
        uint4 o0 = hp[2], o1 = hp[3];     // odd atom w-dups
        uint2 bb = *(const uint2*)(hbase + i * RECB + 64);
        __half2 be2 = u2h2(bb.x), bo2 = u2h2(bb.y);

        __half2 aE01 = be2, aE23 = be2, aO01 = bo2, aO23 = bo2;
        aE01 = __hfma2(u2h2(e0.x), sh01[0], aE01);
        aE01 = __hfma2(u2h2(e0.y), sh01[1], aE01);
        aE01 = __hfma2(u2h2(e0.z), sh01[2], aE01);
        aE01 = __hfma2(u2h2(e0.w), sh01[3], aE01);
        aE01 = __hfma2(u2h2(e1.x), sh01[4], aE01);
        aE01 = __hfma2(u2h2(e1.y), sh01[5], aE01);
        aE01 = __hfma2(u2h2(e1.z), sh01[6], aE01);
        aE01 = __hfma2(u2h2(e1.w), sh01[7], aE01);
        aE23 = __hfma2(u2h2(e0.x), sh23[0], aE23);
        aE23 = __hfma2(u2h2(e0.y), sh23[1], aE23);
        aE23 = __hfma2(u2h2(e0.z), sh23[2], aE23);
        aE23 = __hfma2(u2h2(e0.w), sh23[3], aE23);
        aE23 = __hfma2(u2h2(e1.x), sh23[4], aE23);
        aE23 = __hfma2(u2h2(e1.y), sh23[5], aE23);
        aE23 = __hfma2(u2h2(e1.z), sh23[6], aE23);
        aE23 = __hfma2(u2h2(e1.w), sh23[7], aE23);
        aO01 = __hfma2(u2h2(o0.x), sh01[0], aO01);
        aO01 = __hfma2(u2h2(o0.y), sh01[1], aO01);
        aO01 = __hfma2(u2h2(o0.z), sh01[2], aO01);
        aO01 = __hfma2(u2h2(o0.w), sh01[3], aO01);
        aO01 = __hfma2(u2h2(o1.x), sh01[4], aO01);
        aO01 = __hfma2(u2h2(o1.y), sh01[5], aO01);
        aO01 = __hfma2(u2h2(o1.z), sh01[6], aO01);
        aO01 = __hfma2(u2h2(o1.w), sh01[7], aO01);
        aO23 = __hfma2(u2h2(o0.x), sh23[0], aO23);
        aO23 = __hfma2(u2h2(o0.y), sh23[1], aO23);
        aO23 = __hfma2(u2h2(o0.z), sh23[2], aO23);
        aO23 = __hfma2(u2h2(o0.w), sh23[3], aO23);
        aO23 = __hfma2(u2h2(o1.x), sh23[4], aO23);
        aO23 = __hfma2(u2h2(o1.y), sh23[5], aO23);
        aO23 = __hfma2(u2h2(o1.z), sh23[6], aO23);
        aO23 = __hfma2(u2h2(o1.w), sh23[7], aO23);

        __half2 m01 = __hmax2(aE01, aO01);
        __half2 m23 = __hmax2(aE23, aO23);
        best01 = __hmax2(best01, m01);
        best23 = __hmax2(best23, m23);
        __half2 mm = __hmax2(m01, m23);
        hmx[i] = __hmax(__low2half(mm), __high2half(mm));
    }

    // ---- Pass 2: candidate compaction + exact fp32 verification ----
    float best[PX];
    int batom[PX];
#pragma unroll
    for (int u = 0; u < PX; u++) { best[u] = -FLT_MAX; batom[u] = 0; }

    const char* base = (const char*)sdict32;

#define VERIFY_REC(IDX) do {                                                 \
    int _i = (IDX);                                                          \
    const ulonglong2* _r = (const ulonglong2*)(base + _i * RECB);            \
    ulonglong2 _eA = _r[0], _eB = _r[1], _oA = _r[2], _oB = _r[3];           \
    float2 _bias = *(const float2*)(base + _i * RECB + 64);                  \
    _Pragma("unroll")                                                        \
    for (int _u = 0; _u < PX; _u++) {                                        \
        float _se = atom_score(_eA, _eB, _bias.x, sp[_u]);                   \
        float _so = atom_score(_oA, _oB, _bias.y, sp[_u]);                   \
        if (_se > best[_u]) { best[_u] = _se; batom[_u] = 2 * _i; }          \
        if (_so > best[_u]) { best[_u] = _so; batom[_u] = 2 * _i + 1; }      \
    }                                                                        \
} while (0)

    {
        __half2 bmin2 = __hmin2(best01, best23);
        __half hb = __hmin(__low2half(bmin2), __high2half(bmin2));
        __half th = __float2half_rd(__half2float(hb) - BAND);

        unsigned short cand[CAND_MAX];
        int ccnt = 0;
#pragma unroll 1
        for (int i = 0; i < NREC; i++) {
            if (__hge(hmx[i], th)) {
                if (ccnt < CAND_MAX) cand[ccnt++] = (unsigned short)i;
                else VERIFY_REC(i);   // overflow fallback: exact, in order
            }
        }
#pragma unroll 1
        for (int k = 0; k < ccnt; k++) VERIFY_REC((int)cand[k]);
    }

    // ---- Write partial keys ----
#pragma unroll
    for (int u = 0; u < PX; u++) {
        int n = group * GRPPX + u * TPB + threadIdx.x;
        int atom = q * ATOMS_S + batom[u];
        g_part[q * NXY + n] =
            ((unsigned long long)fmono(best[u]) << 32)
            | (unsigned long long)(65535 - atom);
    }

    // ---- Arrival: last CTA of this pixel group merges ----
    __threadfence();
    __syncthreads();
    if (threadIdx.x == 0) {
        unsigned int old = atomicInc(&g_cnt[group], NQ - 1);  // wraps to 0
        s_last = (old == NQ - 1);
    }
    __syncthreads();
    if (!s_last) return;

    __threadfence();
#pragma unroll
    for (int u = 0; u < PX; u++) {
        int n = group * GRPPX + u * TPB + threadIdx.x;
        unsigned long long key = 0ULL;
#pragma unroll
        for (int qq = 0; qq < NQ; qq++) {
            unsigned long long k2 = g_part[qq * NXY + n];
            if (k2 > key) key = k2;   // ties: lower atom already wins in key
        }
        int atom = 65535 - (int)(key & 0xFFFFULL);
        float score = fmono_inv((unsigned int)(key >> 32));
        float dist2 = fmaxf(s2px[u] - score, 0.0f);
        out[n]           = t2s[atom];
        out[NXY + n]     = b1s[atom];
        out[2 * NXY + n] = sqrtf(dist2);
    }
}

// ---------------------------------------------------------------------------
extern "C" void kernel_launch(void* const* d_in, const int* in_sizes, int n_in,
                              void* d_out, int out_size) {
    const float* slice_signal = (const float*)d_in[0];  // [192,192,16]
    const float* db_mag       = (const float*)d_in[1];  // [4000,16]
    const float* db_t2s_s     = (const float*)d_in[2];  // [4000]
    const float* db_b1s       = (const float*)d_in[3];  // [4000]
    const float* delta_ms     = (const float*)d_in[4];  // [16]
    float* out = (float*)d_out;

    fused_kernel<<<NGRP * NQ, TPB>>>(slice_signal, db_mag, db_t2s_s,
                                     db_b1s, delta_ms, out);
}

// round 16
// speedup vs baseline: 1.6030x; 1.6030x over previous
#include <cuda_runtime.h>
#include <cuda_fp16.h>
#include <math.h>
#include <float.h>
#include <stdint.h>

#define NXY    36864      // 192*192 pixels
#define ETL    16
#define NDICT  4000
#define NSLOT  8          // SE (kept) columns; data-driven, padded with -1
#define TPB    256
#define NPXC   128        // pixels per CTA (8 warps x 16 rows)
#define NCTA   (NXY / NPXC)    // 288
#define NBLK   (NDICT / 16)    // 250 blocks of 16 atoms

#define DEPTH  5e-3f      // screen band: 5x the fp16-input dot-error bound

// SMEM layout (bytes, all 16-aligned)
#define OFF_B    0                    // fp16 dict: 4000 x 16 B = 64000
#define OFF_ZERO 64000                // 16 B of zeros (K-pad row)
#define OFF_A    64016                // fp16 signal tile: 128 x 16 B = 2048
#define OFF_SF32 66064                // fp32 signal: 128 x 32 B = 4096
#define OFF_S2   70160                // fp32 s2: 128 x 4 B = 512
#define SMEM_SZ  70672

__device__ __forceinline__ uint32_t smem_u32(const void* p) {
    uint32_t a;
    asm("{ .reg .u64 t; cvta.to.shared.u64 t, %1; cvt.u32.u64 %0, t; }"
        : "=r"(a) : "l"(p));
    return a;
}

#define LDSM4(R0, R1, R2, R3, ADDR) \
    asm volatile("ldmatrix.sync.aligned.m8n8.x4.shared.b16 {%0,%1,%2,%3}, [%4];" \
                 : "=r"(R0), "=r"(R1), "=r"(R2), "=r"(R3) : "r"(ADDR))

#define MMA16816(D0, D1, D2, D3, A0, A1, A2, A3, B0, B1) \
    asm volatile("mma.sync.aligned.m16n8k16.row.col.f32.f16.f16.f32 " \
                 "{%0,%1,%2,%3}, {%4,%5,%6,%7}, {%8,%9}, {%10,%11,%12,%13};" \
                 : "=f"(D0), "=f"(D1), "=f"(D2), "=f"(D3) \
                 : "r"(A0), "r"(A1), "r"(A2), "r"(A3), "r"(B0), "r"(B1), \
                   "f"(0.0f), "f"(0.0f), "f"(0.0f), "f"(0.0f))

__device__ __forceinline__ void get_cols(const float* __restrict__ delta_ms,
                                         int* cols) {
    int j = 0;
    for (int k = 0; k < ETL; k++) {
        if (delta_ms[k] * 1e-3f < 1e-3f && j < NSLOT) cols[j++] = k;
    }
    for (; j < NSLOT; j++) cols[j] = -1;
}

// Exact fp32 rescore of one (pixel,atom) pair, reading db_mag from global
// (L2-resident) and the pixel's fp32 signal from SMEM. Deterministic op
// order -> self-consistent scores; first-index tie semantics preserved by
// strict > and ascending processing order.
__device__ __forceinline__ void exact_update(
    const float* __restrict__ db_mag, const int* cols, const char* smemc,
    int prow, int atom, float& best, int& bidx)
{
    float v[NSLOT];
    float n2 = 0.0f;
#pragma unroll
    for (int j = 0; j < NSLOT; j++) {
        int c = cols[j];
        float x = (c >= 0) ? db_mag[atom * ETL + c] : 0.0f;
        v[j] = x;
        n2 = fmaf(x, x, n2);
    }
    float inv = 0.0f;
    if (n2 > 0.0f) {
        float r = 1.0f / sqrtf(n2);
        if (isfinite(r)) inv = r;
    }
    const float* sf = (const float*)(smemc + OFF_SF32 + prow * 32);
    float dot = 0.0f, dd = 0.0f;
#pragma unroll
    for (int j = 0; j < NSLOT; j++) {
        float nw = v[j] * inv;
        dot = fmaf(nw, sf[j], dot);
        dd = fmaf(nw, nw, dd);
    }
    float score = fmaf(2.0f, dot, -dd);
    if (score > best) { best = score; bidx = atom; }
}

// ---------------------------------------------------------------------------
// Single kernel. grid = 288 CTAs (128 pixels each), 3 CTAs/SM.
// Loop 1: HMMA screen -> per-pixel max dot. Loop 2: HMMA rescan + exact
// fp32 verification of atoms within DEPTH of the max. No global scratch.
// ---------------------------------------------------------------------------
__global__ void __launch_bounds__(TPB, 3) mma_kernel(
    const float* __restrict__ sig,       // [NXY, ETL]
    const float* __restrict__ db_mag,    // [NDICT, ETL]
    const float* __restrict__ t2s,       // [NDICT]
    const float* __restrict__ b1s,       // [NDICT]
    const float* __restrict__ delta_ms,  // [ETL]
    float* __restrict__ out)             // [3*NXY]: t2 | b1 | min_dist
{
    extern __shared__ __align__(16) char smem[];
    const uint32_t sbase = smem_u32(smem);

    const int tid = threadIdx.x;
    const int wid = tid >> 5;
    const int lane = tid & 31;
    const int blk = blockIdx.x;

    int cols[NSLOT];
    get_cols(delta_ms, cols);

    // ---- Build fp16 dictionary tile (normalization == reference) ----
    for (int a = tid; a < NDICT; a += TPB) {
        float v[NSLOT];
        float n2 = 0.0f;
#pragma unroll
        for (int j = 0; j < NSLOT; j++) {
            int c = cols[j];
            float x = (c >= 0) ? db_mag[a * ETL + c] : 0.0f;
            v[j] = x;
            n2 = fmaf(x, x, n2);
        }
        float inv = 0.0f;
        if (n2 > 0.0f) {
            float r = 1.0f / sqrtf(n2);
            if (isfinite(r)) inv = r;
        }
        __half2 h0 = __floats2half2_rn(v[0] * inv, v[1] * inv);
        __half2 h1 = __floats2half2_rn(v[2] * inv, v[3] * inv);
        __half2 h2 = __floats2half2_rn(v[4] * inv, v[5] * inv);
        __half2 h3 = __floats2half2_rn(v[6] * inv, v[7] * inv);
        uint4 pk;
        pk.x = *(uint32_t*)&h0; pk.y = *(uint32_t*)&h1;
        pk.z = *(uint32_t*)&h2; pk.w = *(uint32_t*)&h3;
        *(uint4*)(smem + OFF_B + a * 16) = pk;
    }

    // ---- Build signal tiles (fp16 for MMA, fp32 for verify, s2) ----
    if (tid < NPXC) {
        int n = blk * NPXC + tid;
        float m[NSLOT];
        float nm2 = 0.0f;
#pragma unroll
        for (int j = 0; j < NSLOT; j++) {
            int c = cols[j];
            float v = (c >= 0) ? sig[n * ETL + c] : 0.0f;
            m[j] = v;
            nm2 = fmaf(v, v, nm2);
        }
        float inv = 0.0f;
        if (nm2 > 0.0f) {
            float r = 1.0f / sqrtf(nm2);
            if (isfinite(r)) inv = r;
        }
        float s[NSLOT];
        float s2 = 0.0f;
#pragma unroll
        for (int j = 0; j < NSLOT; j++) {
            s[j] = m[j] * inv;
            s2 = fmaf(s[j], s[j], s2);
        }
        *(float4*)(smem + OFF_SF32 + tid * 32)      = make_float4(s[0], s[1], s[2], s[3]);
        *(float4*)(smem + OFF_SF32 + tid * 32 + 16) = make_float4(s[4], s[5], s[6], s[7]);
        __half2 h0 = __floats2half2_rn(s[0], s[1]);
        __half2 h1 = __floats2half2_rn(s[2], s[3]);
        __half2 h2 = __floats2half2_rn(s[4], s[5]);
        __half2 h3 = __floats2half2_rn(s[6], s[7]);
        uint4 pk;
        pk.x = *(uint32_t*)&h0; pk.y = *(uint32_t*)&h1;
        pk.z = *(uint32_t*)&h2; pk.w = *(uint32_t*)&h3;
        *(uint4*)(smem + OFF_A + tid * 16) = pk;
        *(float*)(smem + OFF_S2 + tid * 4) = s2;
    }
    if (tid == 0) *(uint4*)(smem + OFF_ZERO) = make_uint4(0, 0, 0, 0);
    __syncthreads();

    // ---- A fragment: 16 pixels x k16 (upper 8 zeros), loaded once ----
    uint32_t a0, a1, a2, a3;
    {
        uint32_t arow = wid * 16 + (lane & 15);
        uint32_t aaddr = (lane < 16) ? (sbase + OFF_A + arow * 16)
                                     : (sbase + OFF_ZERO);
        LDSM4(a0, a1, a2, a3, aaddr);
    }

    // ---- B lane addressing (16 atoms per block via ldmatrix.x4) ----
    const uint32_t grp = lane >> 3;
    const uint32_t oin = (lane & 7) + ((grp == 2) ? 8 : 0);
    const bool live = ((grp & 1) == 0);
    const uint32_t baddr0 = live ? (sbase + OFF_B + oin * 16)
                                 : (sbase + OFF_ZERO);
    const uint32_t bstep = live ? 256 : 0;

    // ---- Loop 1: screen (max dot per pixel-row slot) ----
    float best0 = -FLT_MAX, best1 = -FLT_MAX;
    {
        uint32_t addr = baddr0;
#pragma unroll 1
        for (int i = 0; i < NBLK; i++) {
            uint32_t b0, b1, b2, b3;
            LDSM4(b0, b1, b2, b3, addr);
            addr += bstep;
            float d0, d1, d2, d3;
            MMA16816(d0, d1, d2, d3, a0, a1, a2, a3, b0, b1);
            best0 = fmaxf(best0, fmaxf(d0, d1));
            best1 = fmaxf(best1, fmaxf(d2, d3));
            MMA16816(d0, d1, d2, d3, a0, a1, a2, a3, b2, b3);
            best0 = fmaxf(best0, fmaxf(d0, d1));
            best1 = fmaxf(best1, fmaxf(d2, d3));
        }
    }
    // quad-reduce maxima (rows owned by lane groups of 4)
#pragma unroll
    for (int o = 1; o <= 2; o <<= 1) {
        best0 = fmaxf(best0, __shfl_xor_sync(0xffffffffu, best0, o));
        best1 = fmaxf(best1, __shfl_xor_sync(0xffffffffu, best1, o));
    }
    const float th0 = best0 - DEPTH;
    const float th1 = best1 - DEPTH;

    // ---- Loop 2: rescan + exact fp32 verification of near-max atoms ----
    const int tq = lane & 3;
    const int g = lane >> 2;
    const int prow0 = wid * 16 + g;
    const int prow1 = prow0 + 8;
    float bex0 = -FLT_MAX, bex1 = -FLT_MAX;
    int bi0 = 0, bi1 = 0;
    {
        uint32_t addr = baddr0;
#pragma unroll 1
        for (int i = 0; i < NBLK; i++) {
            uint32_t b0, b1, b2, b3;
            LDSM4(b0, b1, b2, b3, addr);
            addr += bstep;
            int n0 = i * 16;
            float d0, d1, d2, d3;
            MMA16816(d0, d1, d2, d3, a0, a1, a2, a3, b0, b1);
            if (fmaxf(d0, d1) >= th0 || fmaxf(d2, d3) >= th1) {
                int ae = n0 + 2 * tq;
                if (d0 >= th0) exact_update(db_mag, cols, smem, prow0, ae,     bex0, bi0);
                if (d1 >= th0) exact_update(db_mag, cols, smem, prow0, ae + 1, bex0, bi0);
                if (d2 >= th1) exact_update(db_mag, cols, smem, prow1, ae,     bex1, bi1);
                if (d3 >= th1) exact_update(db_mag, cols, smem, prow1, ae + 1, bex1, bi1);
            }
            MMA16816(d0, d1, d2, d3, a0, a1, a2, a3, b2, b3);
            if (fmaxf(d0, d1) >= th0 || fmaxf(d2, d3) >= th1) {
                int ae = n0 + 8 + 2 * tq;
                if (d0 >= th0) exact_update(db_mag, cols, smem, prow0, ae,     bex0, bi0);
                if (d1 >= th0) exact_update(db_mag, cols, smem, prow0, ae + 1, bex0, bi0);
                if (d2 >= th1) exact_update(db_mag, cols, smem, prow1, ae,     bex1, bi1);
                if (d3 >= th1) exact_update(db_mag, cols, smem, prow1, ae + 1, bex1, bi1);
            }
        }
    }

    // ---- Quad-reduce (score, index) with exact tie rules ----
#pragma unroll
    for (int o = 1; o <= 2; o <<= 1) {
        float ob = __shfl_xor_sync(0xffffffffu, bex0, o);
        int oi = __shfl_xor_sync(0xffffffffu, bi0, o);
        if (ob > bex0 || (ob == bex0 && oi < bi0)) { bex0 = ob; bi0 = oi; }
        ob = __shfl_xor_sync(0xffffffffu, bex1, o);
        oi = __shfl_xor_sync(0xffffffffu, bi1, o);
        if (ob > bex1 || (ob == bex1 && oi < bi1)) { bex1 = ob; bi1 = oi; }
    }

    // ---- Writers: one lane per row writes outputs ----
    if (tq == 0) {
        int n = blk * NPXC + prow0;
        float s2 = *(const float*)(smem + OFF_S2 + prow0 * 4);
        out[n]           = t2s[bi0];
        out[NXY + n]     = b1s[bi0];
        out[2 * NXY + n] = sqrtf(fmaxf(s2 - bex0, 0.0f));

        n = blk * NPXC + prow1;
        s2 = *(const float*)(smem + OFF_S2 + prow1 * 4);
        out[n]           = t2s[bi1];
        out[NXY + n]     = b1s[bi1];
        out[2 * NXY + n] = sqrtf(fmaxf(s2 - bex1, 0.0f));
    }
}

// ---------------------------------------------------------------------------
extern "C" void kernel_launch(void* const* d_in, const int* in_sizes, int n_in,
                              void* d_out, int out_size) {
    const float* slice_signal = (const float*)d_in[0];  // [192,192,16]
    const float* db_mag       = (const float*)d_in[1];  // [4000,16]
    const float* db_t2s_s     = (const float*)d_in[2];  // [4000]
    const float* db_b1s       = (const float*)d_in[3];  // [4000]
    const float* delta_ms     = (const float*)d_in[4];  // [16]
    float* out = (float*)d_out;

    cudaFuncSetAttribute(mma_kernel,
                         cudaFuncAttributeMaxDynamicSharedMemorySize, SMEM_SZ);

    mma_kernel<<<NCTA, TPB, SMEM_SZ>>>(slice_signal, db_mag, db_t2s_s,
                                       db_b1s, delta_ms, out);
}